// round 10
// baseline (speedup 1.0000x reference)
#include <cuda_runtime.h>
#include <cuda_fp16.h>
#include <cstdint>

// QuantizedLinear: out[N,OUT] = x[N,IN] @ dequant(w_packed)^T + bias
//   W[o,i] = (nib(o,i)-8)*scale[o]; w_packed int32 has ONE byte payload.
//
// Legacy HMMA mma.sync.m16n8k16 (f32 acc) at the sm_103 legacy-tensor rt16
// ceiling. R9: W pre-dequantized to fp16 in global (zero in-loop unpack),
// A and B fragments via ldmatrix.x4, one sync/iter, fused pre-pass.

#define NR 4096
#define KD 4096
#define OD 4096
#define BM 128
#define BN 128
#define BK 32
#define NIT (KD / BK)
#define NSTG 4

#define ASTR   80                        // 64B data + 16B pad per row
#define ABYTES (BM * ASTR)               // 10240
#define BOFF   ABYTES
#define STG    (2 * ABYTES)              // 20480 per stage
#define SM_TOT (NSTG * STG)              // 81920 dynamic

__device__ __half g_xh[(size_t)NR * KD];
__device__ __half g_wh[(size_t)OD * KD];

__device__ __forceinline__ uint32_t s2u(const void* p) {
    uint32_t a;
    asm("{ .reg .u64 t; cvta.to.shared.u64 t, %1; cvt.u32.u64 %0, t; }"
        : "=r"(a) : "l"(p));
    return a;
}

#define CP16(dst, src) \
    asm volatile("cp.async.cg.shared.global [%0], [%1], 16;" \
                 :: "r"(dst), "l"(src) : "memory")
#define CPCOMMIT() asm volatile("cp.async.commit_group;" ::: "memory")
#define CPWAIT2()  asm volatile("cp.async.wait_group 2;"  ::: "memory")

#define LDSM4(r0, r1, r2, r3, ad) \
    asm volatile("ldmatrix.sync.aligned.m8n8.x4.shared.b16 {%0,%1,%2,%3}, [%4];" \
                 : "=r"(r0), "=r"(r1), "=r"(r2), "=r"(r3) : "r"(ad))

__device__ __forceinline__ void mma16816(float* c, const uint32_t* a,
                                         uint32_t b0, uint32_t b1) {
    asm volatile(
        "mma.sync.aligned.m16n8k16.row.col.f32.f16.f16.f32 "
        "{%0,%1,%2,%3}, {%4,%5,%6,%7}, {%8,%9}, {%0,%1,%2,%3};"
        : "+f"(c[0]), "+f"(c[1]), "+f"(c[2]), "+f"(c[3])
        : "r"(a[0]), "r"(a[1]), "r"(a[2]), "r"(a[3]), "r"(b0), "r"(b1));
}

// int32 (byte payload, 2 nibbles) -> half2 {lo-8, hi-8}, exact bit trick.
__device__ __forceinline__ uint32_t b2h2(int v) {
    uint32_t b = (uint32_t)v & 0xFFu;
    uint32_t d = (b & 0xFu) | ((b << 12) & 0xF0000u) | 0x64006400u;
    const uint32_t C = 0x64086408u;
    __half2 h = __hsub2(*reinterpret_cast<__half2*>(&d),
                        *reinterpret_cast<const __half2*>(&C));
    return *reinterpret_cast<uint32_t*>(&h);
}

// fused pre-pass: blocks [0,XBLKS) convert x fp32->fp16;
// blocks [XBLKS, XBLKS+WBLKS) dequant w int32 -> (q-8) fp16.
#define XBLKS 16384
#define WBLKS 8192
__global__ void prepass(const float* __restrict__ x, const int* __restrict__ wp) {
    if (blockIdx.x < XBLKS) {
        size_t i = ((size_t)blockIdx.x * 256 + threadIdx.x) * 4;
        float4 v = *(const float4*)(x + i);
        *(__half2*)(g_xh + i)     = __floats2half2_rn(v.x, v.y);
        *(__half2*)(g_xh + i + 2) = __floats2half2_rn(v.z, v.w);
    } else {
        size_t i = ((size_t)(blockIdx.x - XBLKS) * 256 + threadIdx.x) * 4;
        int4 v = *(const int4*)(wp + i);
        uint4 o;
        o.x = b2h2(v.x); o.y = b2h2(v.y); o.z = b2h2(v.z); o.w = b2h2(v.w);
        *(uint4*)(g_wh + i * 2) = o;     // each int32 -> 2 halves
    }
}

extern __shared__ char smem[];

__global__ void __launch_bounds__(256, 2)
qmma_kernel(const float* __restrict__ wscale,
            const float* __restrict__ wbias, float* __restrict__ out)
{
    const int t   = threadIdx.x;
    const int wid = t >> 5, lid = t & 31;
    const int wm  = wid >> 2;            // 0..1 -> m offset wm*64
    const int wn  = wid & 3;             // 0..3 -> n offset wn*32
    const int g   = lid >> 2;            // 0..7
    const int c   = lid & 3;             // 0..3
    const int o0  = blockIdx.x * BN;
    const int n0  = blockIdx.y * BM;
    const uint32_t sb = s2u(smem);

    // ldmatrix lane address components (within-tile, stage-invariant)
    const uint32_t a_lane = (uint32_t)(wm * 64 + ((lid >> 3) & 1) * 8 + (lid & 7)) * ASTR
                          + (uint32_t)((lid >> 4) & 1) * 16;
    const uint32_t b_lane = (uint32_t)(wn * 32 + ((lid >> 4) & 1) * 8 + (lid & 7)) * ASTR
                          + (uint32_t)((lid >> 3) & 1) * 16;

    const __half* xg = g_xh + (size_t)n0 * KD;
    const __half* wg = g_wh + (size_t)o0 * KD;

    float acc[4][4][4];
#pragma unroll
    for (int mi = 0; mi < 4; mi++)
#pragma unroll
        for (int nj = 0; nj < 4; nj++)
#pragma unroll
            for (int r = 0; r < 4; r++)
                acc[mi][nj][r] = 0.0f;

    auto issue = [&](int s, int k0) {
        uint32_t sa = sb + s * STG;
#pragma unroll
        for (int j = 0; j < 2; j++) {
            int idx = t + j * 256;           // 0..511
            int r = idx >> 2, cc = idx & 3;  // row, 16B chunk
            CP16(sa + r * ASTR + cc * 16,
                 xg + (size_t)r * KD + k0 + cc * 8);
            CP16(sa + BOFF + r * ASTR + cc * 16,
                 wg + (size_t)r * KD + k0 + cc * 8);
        }
    };

#pragma unroll
    for (int s = 0; s < NSTG - 1; s++) { issue(s, s * BK); CPCOMMIT(); }

#pragma unroll 1
    for (int i = 0; i < NIT; i++) {
        CPWAIT2();
        __syncthreads();

        // refill buffer (i-1)&3 (all reads of it completed before top sync)
        int nx = i + NSTG - 1;
        if (nx < NIT) issue(nx & (NSTG - 1), nx * BK);
        CPCOMMIT();

        const uint32_t A  = sb + (i & (NSTG - 1)) * STG;
        const uint32_t Bb = A + BOFF;

#pragma unroll
        for (int ks = 0; ks < 2; ks++) {
            // B fragments: 2 x ldmatrix.x4 (covers nj pairs, both k-halves)
            uint32_t bf[4][2];
#pragma unroll
            for (int njp = 0; njp < 2; njp++) {
                uint32_t ad = Bb + b_lane + njp * (16 * ASTR) + ks * 32;
                LDSM4(bf[2 * njp][0], bf[2 * njp][1],
                      bf[2 * njp + 1][0], bf[2 * njp + 1][1], ad);
            }
            // A fragments + MMA
#pragma unroll
            for (int mi = 0; mi < 4; mi++) {
                uint32_t a[4];
                uint32_t ad = A + a_lane + mi * (16 * ASTR) + ks * 32;
                LDSM4(a[0], a[1], a[2], a[3], ad);
#pragma unroll
                for (int nj = 0; nj < 4; nj++)
                    mma16816(acc[mi][nj], a, bf[nj][0], bf[nj][1]);
            }
        }
    }

    // ---- epilogue: scale/bias, direct float2 stores ----
#pragma unroll
    for (int nj = 0; nj < 4; nj++) {
        int col = o0 + wn * 32 + nj * 8 + c * 2;
        float s0 = __ldg(wscale + col), s1 = __ldg(wscale + col + 1);
        float b0 = __ldg(wbias + col),  b1 = __ldg(wbias + col + 1);
#pragma unroll
        for (int mi = 0; mi < 4; mi++) {
            int row = n0 + wm * 64 + mi * 16 + g;
            float2 v0, v1;
            v0.x = fmaf(acc[mi][nj][0], s0, b0);
            v0.y = fmaf(acc[mi][nj][1], s1, b1);
            v1.x = fmaf(acc[mi][nj][2], s0, b0);
            v1.y = fmaf(acc[mi][nj][3], s1, b1);
            *(float2*)(out + (size_t)row * OD + col)       = v0;
            *(float2*)(out + (size_t)(row + 8) * OD + col) = v1;
        }
    }
}

extern "C" void kernel_launch(void* const* d_in, const int* in_sizes, int n_in,
                              void* d_out, int out_size)
{
    const float* x      = (const float*)d_in[0];
    const int*   wpk    = (const int*)  d_in[1];
    const float* wscale = (const float*)d_in[2];
    const float* wbias  = (const float*)d_in[3];
    float*       out    = (float*)d_out;

    cudaFuncSetAttribute(qmma_kernel,
                         cudaFuncAttributeMaxDynamicSharedMemorySize, SM_TOT);

    prepass<<<XBLKS + WBLKS, 256>>>(x, wpk);

    dim3 grid(OD / BN, NR / BM);
    qmma_kernel<<<grid, 256, SM_TOT>>>(wscale, wbias, out);
}

// round 12
// speedup vs baseline: 1.6200x; 1.6200x over previous
#include <cuda_runtime.h>
#include <cuda_fp16.h>
#include <cstdint>

// QuantizedLinear: out[N,OUT] = x[N,IN] @ dequant(w_packed)^T + bias
//   W[o,i] = (nib(o,i)-8)*scale[o]; w_packed int32 has ONE byte payload.
//
// Legacy HMMA mma.sync.m16n8k16 (f32 acc). R10 = R4 structure (two syncs,
// cp.async issued at loop bottom so compute-critical shared loads stay at
// the head of the L1tex queue) + ldmatrix.x4 for A fragments + faster
// fused pre-pass.

#define NR 4096
#define KD 4096
#define OD 4096
#define BM 128
#define BN 128
#define BK 32
#define NIT (KD / BK)
#define NSTG 4

#define A_STRIDE 80
#define A_BYTES  (BM * A_STRIDE)        // 10240
#define STG_STR  (A_BYTES + BN * 16)    // 12288
// total 4*12288 = 49152 bytes static smem, 2 CTAs/SM

__device__ __half   g_xh[(size_t)NR * KD];
__device__ uint8_t  g_wb[(size_t)OD * (KD / 2)];

__device__ __forceinline__ uint32_t s2u(const void* p) {
    uint32_t a;
    asm("{ .reg .u64 t; cvta.to.shared.u64 t, %1; cvt.u32.u64 %0, t; }"
        : "=r"(a) : "l"(p));
    return a;
}

#define CP16(dst, src) \
    asm volatile("cp.async.cg.shared.global [%0], [%1], 16;" \
                 :: "r"(dst), "l"(src) : "memory")
#define CPCOMMIT() asm volatile("cp.async.commit_group;" ::: "memory")
#define CPWAIT2()  asm volatile("cp.async.wait_group 2;"  ::: "memory")

#define LDSM4(r0, r1, r2, r3, ad) \
    asm volatile("ldmatrix.sync.aligned.m8n8.x4.shared.b16 {%0,%1,%2,%3}, [%4];" \
                 : "=r"(r0), "=r"(r1), "=r"(r2), "=r"(r3) : "r"(ad))

// packed byte (2 nibbles) -> half2 (lo-8, hi-8), exact.
__device__ __forceinline__ uint32_t nib2h(uint32_t w, uint32_t sel) {
    uint32_t d = __byte_perm(w, 0, sel);            // [b, 0, b, 0]
    d = (d & 0x0000000Fu) | ((d >> 4) & 0x000F0000u) | 0x64006400u;
    const uint32_t C = 0x64086408u;
    __half2 h = __hsub2(*reinterpret_cast<__half2*>(&d),
                        *reinterpret_cast<const __half2*>(&C));
    return *reinterpret_cast<uint32_t*>(&h);
}

__device__ __forceinline__ void mma16816(float* c, const uint32_t* a,
                                         uint32_t b0, uint32_t b1) {
    asm volatile(
        "mma.sync.aligned.m16n8k16.row.col.f32.f16.f16.f32 "
        "{%0,%1,%2,%3}, {%4,%5,%6,%7}, {%8,%9}, {%0,%1,%2,%3};"
        : "+f"(c[0]), "+f"(c[1]), "+f"(c[2]), "+f"(c[3])
        : "r"(a[0]), "r"(a[1]), "r"(a[2]), "r"(a[3]), "r"(b0), "r"(b1));
}

// fused pre-pass: blocks [0,XBLKS) convert x fp32->fp16 (8 floats/thread);
// blocks [XBLKS,XBLKS+WBLKS) repack w int32(byte payload)->uint8.
#define XBLKS 8192
#define WBLKS 2048
__global__ void prepass(const float* __restrict__ x, const int* __restrict__ wp) {
    if (blockIdx.x < XBLKS) {
        size_t i = ((size_t)blockIdx.x * 256 + threadIdx.x) * 8;
        float4 v0 = *(const float4*)(x + i);
        float4 v1 = *(const float4*)(x + i + 4);
        *(__half2*)(g_xh + i)     = __floats2half2_rn(v0.x, v0.y);
        *(__half2*)(g_xh + i + 2) = __floats2half2_rn(v0.z, v0.w);
        *(__half2*)(g_xh + i + 4) = __floats2half2_rn(v1.x, v1.y);
        *(__half2*)(g_xh + i + 6) = __floats2half2_rn(v1.z, v1.w);
    } else {
        size_t i = ((size_t)(blockIdx.x - XBLKS) * 256 + threadIdx.x) * 16;
        const int4* src = (const int4*)(wp + i);
        uint4 o;
        int4 v0 = src[0], v1 = src[1], v2 = src[2], v3 = src[3];
        o.x = (uint32_t)(v0.x & 0xFF) | ((uint32_t)(v0.y & 0xFF) << 8) |
              ((uint32_t)(v0.z & 0xFF) << 16) | ((uint32_t)v0.w << 24);
        o.y = (uint32_t)(v1.x & 0xFF) | ((uint32_t)(v1.y & 0xFF) << 8) |
              ((uint32_t)(v1.z & 0xFF) << 16) | ((uint32_t)v1.w << 24);
        o.z = (uint32_t)(v2.x & 0xFF) | ((uint32_t)(v2.y & 0xFF) << 8) |
              ((uint32_t)(v2.z & 0xFF) << 16) | ((uint32_t)v2.w << 24);
        o.w = (uint32_t)(v3.x & 0xFF) | ((uint32_t)(v3.y & 0xFF) << 8) |
              ((uint32_t)(v3.z & 0xFF) << 16) | ((uint32_t)v3.w << 24);
        *(uint4*)(g_wb + i) = o;
    }
}

__global__ void __launch_bounds__(256, 2)
qmma_kernel(const float* __restrict__ wscale,
            const float* __restrict__ wbias, float* __restrict__ out)
{
    __shared__ __align__(16) char sm[NSTG * STG_STR];

    const int t   = threadIdx.x;
    const int wid = t >> 5, lid = t & 31;
    const int wm  = wid >> 2;            // 0..1 -> m offset wm*64
    const int wn  = wid & 3;             // 0..3 -> n offset wn*32
    const int g   = lid >> 2;            // 0..7
    const int c   = lid & 3;             // 0..3
    const int o0  = blockIdx.x * BN;
    const int n0  = blockIdx.y * BM;
    const uint32_t sb = s2u(sm);
    const uint32_t sel = 0x4040u | ((uint32_t)c << 8) | (uint32_t)c;

    // ldmatrix lane address (A): rows wm*64 + (lid>>3&1)*8 + (lid&7),
    // k-half column select (lid>>4&1)*16 bytes.
    const uint32_t a_lane = (uint32_t)(wm * 64 + ((lid >> 3) & 1) * 8 + (lid & 7)) * A_STRIDE
                          + (uint32_t)((lid >> 4) & 1) * 16;

    const __half*  xg = g_xh + (size_t)n0 * KD;
    const uint8_t* wg = g_wb + (size_t)o0 * (KD / 2);

    float acc[4][4][4];
#pragma unroll
    for (int mi = 0; mi < 4; mi++)
#pragma unroll
        for (int nj = 0; nj < 4; nj++)
#pragma unroll
            for (int r = 0; r < 4; r++)
                acc[mi][nj][r] = 0.0f;

    auto issue = [&](int s, int k0) {
        uint32_t sa = sb + s * STG_STR;
#pragma unroll
        for (int j = 0; j < 2; j++) {
            int idx = t + j * 256;           // 0..511
            int r = idx >> 2, cc = idx & 3;  // row, 16B-chunk
            CP16(sa + r * A_STRIDE + cc * 16,
                 xg + (size_t)r * KD + k0 + cc * 8);
        }
        if (t < BN)
            CP16(sa + A_BYTES + t * 16, wg + (size_t)t * (KD / 2) + (k0 >> 1));
    };

#pragma unroll
    for (int s = 0; s < NSTG - 1; s++) { issue(s, s * BK); CPCOMMIT(); }

#pragma unroll 1
    for (int i = 0; i < NIT; i++) {
        CPWAIT2();
        __syncthreads();

        const uint32_t A  = sb + (i & (NSTG - 1)) * STG_STR;
        const uint32_t Bb = A + A_BYTES;

        // B fragments: one lds.128 per nj (broadcast in quad), unpack bytes.
        uint32_t breg[2][4][2];
#pragma unroll
        for (int nj = 0; nj < 4; nj++) {
            int row = wn * 32 + nj * 8 + g;
            uint4 w;
            asm volatile("ld.shared.v4.u32 {%0,%1,%2,%3}, [%4];"
                         : "=r"(w.x), "=r"(w.y), "=r"(w.z), "=r"(w.w)
                         : "r"(Bb + row * 16));
            breg[0][nj][0] = nib2h(w.x, sel);
            breg[0][nj][1] = nib2h(w.y, sel);
            breg[1][nj][0] = nib2h(w.z, sel);
            breg[1][nj][1] = nib2h(w.w, sel);
        }

#pragma unroll
        for (int ks = 0; ks < 2; ks++) {
#pragma unroll
            for (int mi = 0; mi < 4; mi++) {
                uint32_t a[4];
                uint32_t ad = A + a_lane + mi * (16 * A_STRIDE) + ks * 32;
                LDSM4(a[0], a[1], a[2], a[3], ad);
#pragma unroll
                for (int nj = 0; nj < 4; nj++)
                    mma16816(acc[mi][nj], a, breg[ks][nj][0], breg[ks][nj][1]);
            }
        }
        __syncthreads();

        // cp.async at loop bottom: critical LDS/LDSM of the NEXT iter stay
        // ahead of these global loads in the L1tex queue.
        int nx = i + NSTG - 1;
        if (nx < NIT) issue(nx & (NSTG - 1), nx * BK);
        CPCOMMIT();
    }

    // ---- epilogue: scale/bias, direct float2 stores ----
#pragma unroll
    for (int nj = 0; nj < 4; nj++) {
        int col = o0 + wn * 32 + nj * 8 + c * 2;
        float s0 = __ldg(wscale + col), s1 = __ldg(wscale + col + 1);
        float b0 = __ldg(wbias + col),  b1 = __ldg(wbias + col + 1);
#pragma unroll
        for (int mi = 0; mi < 4; mi++) {
            int row = n0 + wm * 64 + mi * 16 + g;
            float2 v0, v1;
            v0.x = fmaf(acc[mi][nj][0], s0, b0);
            v0.y = fmaf(acc[mi][nj][1], s1, b1);
            v1.x = fmaf(acc[mi][nj][2], s0, b0);
            v1.y = fmaf(acc[mi][nj][3], s1, b1);
            *(float2*)(out + (size_t)row * OD + col)       = v0;
            *(float2*)(out + (size_t)(row + 8) * OD + col) = v1;
        }
    }
}

extern "C" void kernel_launch(void* const* d_in, const int* in_sizes, int n_in,
                              void* d_out, int out_size)
{
    const float* x      = (const float*)d_in[0];
    const int*   wpk    = (const int*)  d_in[1];
    const float* wscale = (const float*)d_in[2];
    const float* wbias  = (const float*)d_in[3];
    float*       out    = (float*)d_out;

    prepass<<<XBLKS + WBLKS, 256>>>(x, wpk);

    dim3 grid(OD / BN, NR / BM);
    qmma_kernel<<<grid, 256>>>(wscale, wbias, out);
}